// round 7
// baseline (speedup 1.0000x reference)
#include <cuda_runtime.h>

#define BB 8
#define C 256
#define HID 64
#define G 16
#define KK 9
#define GKK 144
#define HW 4096
#define IMG_W 64
#define IMG_H 64

typedef unsigned long long u64;

__device__ __align__(16) float g_kmap[BB * GKK * HW];   // 18 MB scratch

__device__ __forceinline__ u64 ffma2(u64 a, u64 b, u64 c) {
    u64 d;
    asm("fma.rn.f32x2 %0, %1, %2, %3;" : "=l"(d) : "l"(a), "l"(b), "l"(c));
    return d;
}
__device__ __forceinline__ u64 pk(float lo, float hi) {
    u64 r;
    asm("mov.b64 %0, {%1, %2};" : "=l"(r) : "f"(lo), "f"(hi));
    return r;
}
__device__ __forceinline__ float lo32(u64 v) { return __uint_as_float((unsigned)(v & 0xFFFFFFFFu)); }
__device__ __forceinline__ float hi32(u64 v) { return __uint_as_float((unsigned)(v >> 32)); }

// ---------------------------------------------------------------------------
// Fused kernel: stage1 (reduce+relu) -> smem hid -> stage2 (span) -> g_kmap
// Both GEMM phases use packed fma.rn.f32x2 (2 FMA/instr), weights broadcast
// from smem as float4 and duplicated into pairs via ALU-pipe movs.
// ---------------------------------------------------------------------------
__global__ __launch_bounds__(256, 2) void k_fused(const float* __restrict__ x,
                                                  const float* __restrict__ wr,
                                                  const float* __restrict__ br,
                                                  const float* __restrict__ wsp,
                                                  const float* __restrict__ bs) {
    extern __shared__ __align__(16) float sm[];
    float* ws    = sm;              // [2][2048]  phase A w chunks
    float* xs    = sm + 4096;       // [2][4096]  phase A x chunks
    float* hid   = sm;              // [64][128]  phase B (reuses A region)
    float* wsp_s = sm + 12288;      // [144][64]

    const int tid = threadIdx.x;
    const int b  = blockIdx.x >> 5;
    const int pt = (blockIdx.x & 31) << 7;
    const int pg = tid & 31;
    const int og = tid >> 5;

    // stream w_span into smem (float4, coalesced)
#pragma unroll
    for (int i = 0; i < 9; i++) {
        int lin = (tid + i * 256) * 4;
        *(float4*)(wsp_s + lin) = *(const float4*)(wsp + lin);
    }

    // ---- phase A prologue: chunk 0 -> buffer 0 ----
#pragma unroll
    for (int i = 0; i < 4; i++) {
        int lin = tid + i * 256;
        int cc = lin >> 5, p4 = lin & 31;
        *(float4*)(xs + cc * 128 + p4 * 4) =
            *(const float4*)(x + ((size_t)(b * C + cc)) * HW + pt + p4 * 4);
    }
#pragma unroll
    for (int i = 0; i < 8; i++) {
        int lin = tid + i * 256;        // = o*32 + cc
        int o = lin >> 5, cc = lin & 31;
        ws[lin] = wr[o * C + cc];
    }
    __syncthreads();

    u64 acc[8][2];
#pragma unroll
    for (int i = 0; i < 8; i++) { acc[i][0] = 0ull; acc[i][1] = 0ull; }

    // ---- phase A: double buffered, FFMA2 ----
    for (int ck = 0; ck < 8; ck++) {
        const int cur = ck & 1;
        float4 xr[4];
        float  wrr[8];
        if (ck < 7) {
#pragma unroll
            for (int i = 0; i < 4; i++) {
                int lin = tid + i * 256;
                int cc = lin >> 5, p4 = lin & 31;
                xr[i] = *(const float4*)(x + ((size_t)(b * C + (ck + 1) * 32 + cc)) * HW + pt + p4 * 4);
            }
#pragma unroll
            for (int i = 0; i < 8; i++) {
                int lin = tid + i * 256;
                int o = lin >> 5, cc = lin & 31;
                wrr[i] = wr[o * C + (ck + 1) * 32 + cc];
            }
        }
        const float* xb = xs + cur * 4096;
        const float* wb = ws + cur * 2048;
#pragma unroll
        for (int cb = 0; cb < 8; cb++) {
            ulonglong2 xq[4];
#pragma unroll
            for (int i = 0; i < 4; i++)
                xq[i] = *(const ulonglong2*)(xb + (cb * 4 + i) * 128 + pg * 4);
#pragma unroll
            for (int om = 0; om < 8; om++) {
                float4 wv = *(const float4*)(wb + (og * 8 + om) * 32 + cb * 4); // uniform bcast
                u64 w0 = pk(wv.x, wv.x), w1 = pk(wv.y, wv.y);
                u64 w2 = pk(wv.z, wv.z), w3 = pk(wv.w, wv.w);
                acc[om][0] = ffma2(w0, xq[0].x, acc[om][0]);
                acc[om][1] = ffma2(w0, xq[0].y, acc[om][1]);
                acc[om][0] = ffma2(w1, xq[1].x, acc[om][0]);
                acc[om][1] = ffma2(w1, xq[1].y, acc[om][1]);
                acc[om][0] = ffma2(w2, xq[2].x, acc[om][0]);
                acc[om][1] = ffma2(w2, xq[2].y, acc[om][1]);
                acc[om][0] = ffma2(w3, xq[3].x, acc[om][0]);
                acc[om][1] = ffma2(w3, xq[3].y, acc[om][1]);
            }
        }
        if (ck < 7) {
            const int nxt = cur ^ 1;
#pragma unroll
            for (int i = 0; i < 4; i++) {
                int lin = tid + i * 256;
                int cc = lin >> 5, p4 = lin & 31;
                *(float4*)(xs + nxt * 4096 + cc * 128 + p4 * 4) = xr[i];
            }
#pragma unroll
            for (int i = 0; i < 8; i++)
                ws[nxt * 2048 + tid + i * 256] = wrr[i];
        }
        __syncthreads();
    }

    // ---- phase A epilogue: relu+bias -> smem hid ----
#pragma unroll
    for (int om = 0; om < 8; om++) {
        int o = og * 8 + om;
        float bias = __ldg(br + o);
        float4 r;
        r.x = fmaxf(lo32(acc[om][0]) + bias, 0.f);
        r.y = fmaxf(hi32(acc[om][0]) + bias, 0.f);
        r.z = fmaxf(lo32(acc[om][1]) + bias, 0.f);
        r.w = fmaxf(hi32(acc[om][1]) + bias, 0.f);
        *(float4*)(hid + o * 128 + pg * 4) = r;
    }
    __syncthreads();

    // ---- phase B: span GEMM, FFMA2 ----
    u64 acc2[18][2];
#pragma unroll
    for (int i = 0; i < 18; i++) { acc2[i][0] = 0ull; acc2[i][1] = 0ull; }

#pragma unroll 4
    for (int hb = 0; hb < 16; hb++) {
        ulonglong2 xq[4];
#pragma unroll
        for (int i = 0; i < 4; i++)
            xq[i] = *(const ulonglong2*)(hid + (hb * 4 + i) * 128 + pg * 4);
#pragma unroll
        for (int om = 0; om < 18; om++) {
            float4 wv = *(const float4*)(wsp_s + (og * 18 + om) * 64 + hb * 4); // uniform bcast
            u64 w0 = pk(wv.x, wv.x), w1 = pk(wv.y, wv.y);
            u64 w2 = pk(wv.z, wv.z), w3 = pk(wv.w, wv.w);
            acc2[om][0] = ffma2(w0, xq[0].x, acc2[om][0]);
            acc2[om][1] = ffma2(w0, xq[0].y, acc2[om][1]);
            acc2[om][0] = ffma2(w1, xq[1].x, acc2[om][0]);
            acc2[om][1] = ffma2(w1, xq[1].y, acc2[om][1]);
            acc2[om][0] = ffma2(w2, xq[2].x, acc2[om][0]);
            acc2[om][1] = ffma2(w2, xq[2].y, acc2[om][1]);
            acc2[om][0] = ffma2(w3, xq[3].x, acc2[om][0]);
            acc2[om][1] = ffma2(w3, xq[3].y, acc2[om][1]);
        }
    }
#pragma unroll
    for (int om = 0; om < 18; om++) {
        int o = og * 18 + om;
        float bias = __ldg(bs + o);
        float4 r;
        r.x = lo32(acc2[om][0]) + bias;
        r.y = hi32(acc2[om][0]) + bias;
        r.z = lo32(acc2[om][1]) + bias;
        r.w = hi32(acc2[om][1]) + bias;
        *(float4*)(g_kmap + ((size_t)(b * GKK + o)) * HW + pt + pg * 4) = r;
    }
}

// ---------------------------------------------------------------------------
// Kernel 3: involution, full group (16 ch) per CTA, channel-pair interleaved.
// CTA = (strip of 8 rows, g, b). smem [8 chpair][10 rows][68 cols][2] = 43.5KB.
// 9 kmap LDG.128 hoisted to entry -> in flight across halo load + barrier.
// Halo stores are float2 (interleaved layout is only 8B-aligned there).
// ---------------------------------------------------------------------------
__global__ __launch_bounds__(256) void k_invol(const float* __restrict__ x,
                                               float* __restrict__ out) {
    __shared__ __align__(16) float sm[8 * 10 * 68 * 2];   // 43.5 KB
    const int tid   = threadIdx.x;
    const int strip = blockIdx.x;           // 0..7
    const int g = blockIdx.y;
    const int b = blockIdx.z;
    const int chbase = g * 16;

    const int cph = tid >> 7;          // 0..1
    const int rr  = (tid >> 4) & 7;    // output row within strip
    const int t4  = tid & 15;          // colgroup (4 cols)
    const int R0  = strip * 8 + rr;
    const int X0  = t4 * 4;

    // --- issue all 9 kmap loads immediately (hidden behind halo load) ---
    const float* kbase = g_kmap + ((size_t)(b * G + g)) * KK * HW + R0 * IMG_W + X0;
    float4 km[9];
#pragma unroll
    for (int k = 0; k < 9; k++)
        km[k] = *(const float4*)(kbase + (size_t)k * HW);

    // zero edge pair-columns (smem col 0 and 65) for all (cp, r)
    if (tid < 160) {
        int cp = tid / 20, rem = tid % 20;
        int r = rem >> 1, side = rem & 1;
        int col = side ? 65 : 0;
        *(u64*)&sm[((cp * 10 + r) * 68 + col) * 2] = 0ull;
    }

    // load 8 chpairs x 10 rows x 64 cols, interleaving channel pairs
#pragma unroll
    for (int it = 0; it < 5; it++) {
        int lin = tid + it * 256;          // 1280 items total
        int cp  = lin / 160;
        int rem = lin - cp * 160;
        int r = rem >> 4, c4 = rem & 15;
        int R = strip * 8 + r - 1;
        float4 a = make_float4(0.f, 0.f, 0.f, 0.f);
        float4 c = a;
        if ((unsigned)R < (unsigned)IMG_H) {
            const float* p0 = x + ((size_t)(b * C + chbase + cp * 2)) * HW + R * IMG_W + c4 * 4;
            a = *(const float4*)p0;
            c = *(const float4*)(p0 + HW);
        }
        float* d = &sm[((cp * 10 + r) * 68 + 1 + c4 * 4) * 2];  // 8B-aligned only
        ((float2*)d)[0] = make_float2(a.x, c.x);
        ((float2*)d)[1] = make_float2(a.y, c.y);
        ((float2*)d)[2] = make_float2(a.z, c.z);
        ((float2*)d)[3] = make_float2(a.w, c.w);
    }
    __syncthreads();

#pragma unroll
    for (int half = 0; half < 2; half++) {
        u64 acc[2][4];
#pragma unroll
        for (int cp = 0; cp < 2; cp++)
#pragma unroll
            for (int j = 0; j < 4; j++) acc[cp][j] = 0ull;

#pragma unroll
        for (int dy = 0; dy < 3; dy++) {
            u64 km2[3][4];
#pragma unroll
            for (int dx = 0; dx < 3; dx++) {
                float4 kmv = km[dy * 3 + dx];
                km2[dx][0] = pk(kmv.x, kmv.x);
                km2[dx][1] = pk(kmv.y, kmv.y);
                km2[dx][2] = pk(kmv.z, kmv.z);
                km2[dx][3] = pk(kmv.w, kmv.w);
            }
#pragma unroll
            for (int cp = 0; cp < 2; cp++) {
                const int cpi = cph * 4 + half * 2 + cp;
                const float* srow = &sm[((cpi * 10 + rr + dy) * 68 + t4 * 4) * 2];
                ulonglong2 q0 = *(const ulonglong2*)(srow);
                ulonglong2 q1 = *(const ulonglong2*)(srow + 4);
                ulonglong2 q2 = *(const ulonglong2*)(srow + 8);
                u64 p0 = q0.x, p1 = q0.y, p2 = q1.x, p3 = q1.y, p4 = q2.x, p5 = q2.y;
                acc[cp][0] = ffma2(p0, km2[0][0], acc[cp][0]);
                acc[cp][0] = ffma2(p1, km2[1][0], acc[cp][0]);
                acc[cp][0] = ffma2(p2, km2[2][0], acc[cp][0]);
                acc[cp][1] = ffma2(p1, km2[0][1], acc[cp][1]);
                acc[cp][1] = ffma2(p2, km2[1][1], acc[cp][1]);
                acc[cp][1] = ffma2(p3, km2[2][1], acc[cp][1]);
                acc[cp][2] = ffma2(p2, km2[0][2], acc[cp][2]);
                acc[cp][2] = ffma2(p3, km2[1][2], acc[cp][2]);
                acc[cp][2] = ffma2(p4, km2[2][2], acc[cp][2]);
                acc[cp][3] = ffma2(p3, km2[0][3], acc[cp][3]);
                acc[cp][3] = ffma2(p4, km2[1][3], acc[cp][3]);
                acc[cp][3] = ffma2(p5, km2[2][3], acc[cp][3]);
            }
        }

#pragma unroll
        for (int cp = 0; cp < 2; cp++) {
            const int ch = chbase + (cph * 4 + half * 2 + cp) * 2;
            float4 ev, od;
            ev.x = lo32(acc[cp][0]); od.x = hi32(acc[cp][0]);
            ev.y = lo32(acc[cp][1]); od.y = hi32(acc[cp][1]);
            ev.z = lo32(acc[cp][2]); od.z = hi32(acc[cp][2]);
            ev.w = lo32(acc[cp][3]); od.w = hi32(acc[cp][3]);
            float* obase = out + ((size_t)(b * C + ch)) * HW + R0 * IMG_W + X0;
            *(float4*)obase = ev;
            *(float4*)(obase + HW) = od;
        }
    }
}

// ---------------------------------------------------------------------------
extern "C" void kernel_launch(void* const* d_in, const int* in_sizes, int n_in,
                              void* d_out, int out_size) {
    const float* x   = (const float*)d_in[0];
    const float* wr  = (const float*)d_in[1];
    const float* br  = (const float*)d_in[2];
    const float* wsp = (const float*)d_in[3];
    const float* bs  = (const float*)d_in[4];
    float* out = (float*)d_out;

    static int smem_set = 0;
    if (!smem_set) {
        cudaFuncSetAttribute(k_fused, cudaFuncAttributeMaxDynamicSharedMemorySize, 86016);
        smem_set = 1;
    }

    k_fused<<<BB * (HW / 128), 256, 86016>>>(x, wr, br, wsp, bs);
    dim3 g3(8, G, BB);   // (strip, g, b)
    k_invol<<<g3, 256>>>(x, out);
}

// round 9
// speedup vs baseline: 1.3847x; 1.3847x over previous
#include <cuda_runtime.h>
#include <cstdint>

#define BB 8
#define C 256
#define G 16
#define KK 9
#define GKK 144
#define HW 4096
#define IMG_W 64
#define IMG_H 64

typedef unsigned long long u64;
typedef unsigned int u32;

__device__ __align__(16) float g_kmap[BB * GKK * HW];

// ---------- scalar helpers ----------
__device__ __forceinline__ u64 ffma2(u64 a, u64 b, u64 c) {
    u64 d; asm("fma.rn.f32x2 %0, %1, %2, %3;" : "=l"(d) : "l"(a), "l"(b), "l"(c)); return d;
}
__device__ __forceinline__ u64 pk(float lo, float hi) {
    u64 r; asm("mov.b64 %0, {%1, %2};" : "=l"(r) : "f"(lo), "f"(hi)); return r;
}
__device__ __forceinline__ float lo32(u64 v) { return __uint_as_float((u32)v); }
__device__ __forceinline__ float hi32(u64 v) { return __uint_as_float((u32)(v >> 32)); }
__device__ __forceinline__ u32 bf2(float lo, float hi) {
    u32 r; asm("cvt.rn.bf16x2.f32 %0, %1, %2;" : "=r"(r) : "f"(hi), "f"(lo)); return r;
}
// split pair into bf16 hi part + bf16 residual lo part
__device__ __forceinline__ void split2(float v0, float v1, u32& h2, u32& l2) {
    h2 = bf2(v0, v1);
    l2 = bf2(v0 - __uint_as_float(h2 << 16), v1 - __uint_as_float(h2 & 0xFFFF0000u));
}
__device__ __forceinline__ void cvt4(float4 v, u64& h, u64& l) {
    u32 h0, l0, h1, l1;
    split2(v.x, v.y, h0, l0);
    split2(v.z, v.w, h1, l1);
    h = (u64)h0 | ((u64)h1 << 32);
    l = (u64)l0 | ((u64)l1 << 32);
}
__device__ __forceinline__ u32 smem_u32(const void* p) {
    u32 a; asm("{ .reg .u64 t; cvta.to.shared.u64 t, %1; cvt.u32.u64 %0, t; }" : "=r"(a) : "l"(p));
    return a;
}

// mma m16n8k16 bf16 -> f32, accumulate in place
#define MMA(d, a, b0, b1) \
    asm volatile("mma.sync.aligned.m16n8k16.row.col.f32.bf16.bf16.f32 " \
        "{%0,%1,%2,%3}, {%4,%5,%6,%7}, {%8,%9}, {%0,%1,%2,%3};" \
        : "+f"((d)[0]), "+f"((d)[1]), "+f"((d)[2]), "+f"((d)[3]) \
        : "r"((a)[0]), "r"((a)[1]), "r"((a)[2]), "r"((a)[3]), "r"(b0), "r"(b1))

#define LDSM4T(r, addr) \
    asm volatile("ldmatrix.sync.aligned.m8n8.x4.trans.shared.b16 {%0,%1,%2,%3}, [%4];" \
        : "=r"((r)[0]), "=r"((r)[1]), "=r"((r)[2]), "=r"((r)[3]) : "r"(addr))

// smem byte layout
#define OFF_XH   0        // 2 bufs x [32 k][128 px] bf16 (256B rows) = 2*8192
#define OFF_XL   16384
#define OFF_W1H  32768    // 2 bufs x [64 n][40 k] bf16 (80B rows) = 2*5120
#define OFF_W1L  43008
#define OFF_WSPH 53248    // [144 n][72 k] bf16 (144B rows) = 20736
#define OFF_WSPL 73984
#define SM_TOTAL 94720

// ---------------------------------------------------------------------------
// k_gemm: both 1x1 convs as HMMA GEMMs, bf16 split-2 (hh+hl+lh).
// CTA = 128 px tile, 4 warps; warp = 32 px rows x all N.
// hid stays in registers between the two GEMMs (C-frag == A-frag layout).
// ---------------------------------------------------------------------------
__global__ __launch_bounds__(128, 2)
void k_gemm(const float* __restrict__ x, const float* __restrict__ wr,
            const float* __restrict__ br, const float* __restrict__ wsp,
            const float* __restrict__ bs) {
    extern __shared__ __align__(16) char smem[];
    const int tid = threadIdx.x, wid = tid >> 5, lane = tid & 31;
    const int b = blockIdx.x >> 5, pt = (blockIdx.x & 31) << 7;
    const u32 sbase = smem_u32(smem);

    // ---- w_span -> smem bf16 hi/lo, rows padded to 72 elems (144B) ----
#pragma unroll
    for (int i = 0; i < 18; i++) {
        int f4 = tid + i * 128;                    // 2304 float4 total
        float4 v = *(const float4*)(wsp + f4 * 4);
        int n = f4 >> 4, kc = (f4 & 15) * 4;
        u64 h, l;
        cvt4(v, h, l);
        *(u64*)(smem + OFF_WSPH + n * 144 + kc * 2) = h;
        *(u64*)(smem + OFF_WSPL + n * 144 + kc * 2) = l;
    }

    // ---- prologue: chunk 0 of x and w_reduce ----
    {
        const int c = tid >> 2, pxb = (tid & 3) * 32;
        const float* xsrc = x + ((size_t)(b * C + c)) * HW + pt + pxb;
        const int csw = (c & 7) << 3;
#pragma unroll
        for (int q = 0; q < 8; q++) {
            float4 v = *(const float4*)(xsrc + q * 4);
            int col = (pxb + q * 4) ^ csw;
            u64 h, l;
            cvt4(v, h, l);
            *(u64*)(smem + OFF_XH + c * 256 + col * 2) = h;
            *(u64*)(smem + OFF_XL + c * 256 + col * 2) = l;
        }
        const int n = tid >> 1, koff = (tid & 1) * 16;
#pragma unroll
        for (int q = 0; q < 4; q++) {
            float4 v = *(const float4*)(wr + n * C + koff + q * 4);
            u64 h, l;
            cvt4(v, h, l);
            *(u64*)(smem + OFF_W1H + n * 80 + (koff + q * 4) * 2) = h;
            *(u64*)(smem + OFF_W1L + n * 80 + (koff + q * 4) * 2) = l;
        }
    }
    __syncthreads();

    float acc1[2][8][4];
#pragma unroll
    for (int i = 0; i < 2; i++)
#pragma unroll
        for (int j = 0; j < 8; j++)
#pragma unroll
            for (int q = 0; q < 4; q++) acc1[i][j][q] = 0.f;

    const int m00 = wid * 32;
    const int grp = lane >> 3, li = lane & 7;
    const int krow_off = ((grp & 2) << 2) + li;       // +8 for mats 2,3
    const int coladd = (grp & 1) << 3;                // +8 cols for mats 1,3
    const u32 bB1 = (u32)((lane >> 2) * 80 + ((lane & 3) << 2));
    const u32 bB2 = (u32)((lane >> 2) * 144 + ((lane & 3) << 2));

    // ---- stage 1: K=256 in 8 chunks of 32, double buffered ----
#pragma unroll 1
    for (int ck = 0; ck < 8; ck++) {
        const int cur = ck & 1, nxt = cur ^ 1;
        float4 xr[8], wrr[4];
        if (ck < 7) {
            const int c = tid >> 2, pxb = (tid & 3) * 32;
            const float* xsrc = x + ((size_t)(b * C + (ck + 1) * 32 + c)) * HW + pt + pxb;
#pragma unroll
            for (int q = 0; q < 8; q++) xr[q] = *(const float4*)(xsrc + q * 4);
            const int n = tid >> 1, koff = (tid & 1) * 16;
#pragma unroll
            for (int q = 0; q < 4; q++)
                wrr[q] = *(const float4*)(wr + n * C + (ck + 1) * 32 + koff + q * 4);
        }
        const u32 sxh = sbase + OFF_XH + cur * 8192;
        const char* w1h = smem + OFF_W1H + cur * 5120;
        const char* w1l = smem + OFF_W1L + cur * 5120;

#pragma unroll
        for (int ks = 0; ks < 2; ks++) {
            const int kb = ks * 16;
            u32 AH[2][4], AL[2][4];
#pragma unroll
            for (int mi = 0; mi < 2; mi++) {
                int col = (m00 + mi * 16 + coladd) ^ (li << 3);
                u32 ah = sxh + (u32)((kb + krow_off) * 256 + col * 2);
                LDSM4T(AH[mi], ah);
                LDSM4T(AL[mi], ah + 16384);   // XL plane at fixed +16384
            }
#pragma unroll
            for (int nj = 0; nj < 8; nj++) {
                u32 off = bB1 + nj * 640 + kb * 2;
                u32 bh0 = *(const u32*)(w1h + off);
                u32 bh1 = *(const u32*)(w1h + off + 16);
                u32 bl0 = *(const u32*)(w1l + off);
                u32 bl1 = *(const u32*)(w1l + off + 16);
#pragma unroll
                for (int mi = 0; mi < 2; mi++) {
                    MMA(acc1[mi][nj], AH[mi], bh0, bh1);
                    MMA(acc1[mi][nj], AH[mi], bl0, bl1);
                    MMA(acc1[mi][nj], AL[mi], bh0, bh1);
                }
            }
        }
        if (ck < 7) {
            const int c = tid >> 2, pxb = (tid & 3) * 32;
            const int csw = (c & 7) << 3;
#pragma unroll
            for (int q = 0; q < 8; q++) {
                int col = (pxb + q * 4) ^ csw;
                u64 h, l;
                cvt4(xr[q], h, l);
                *(u64*)(smem + OFF_XH + nxt * 8192 + c * 256 + col * 2) = h;
                *(u64*)(smem + OFF_XL + nxt * 8192 + c * 256 + col * 2) = l;
            }
            const int n = tid >> 1, koff = (tid & 1) * 16;
#pragma unroll
            for (int q = 0; q < 4; q++) {
                u64 h, l;
                cvt4(wrr[q], h, l);
                *(u64*)(smem + OFF_W1H + nxt * 5120 + n * 80 + (koff + q * 4) * 2) = h;
                *(u64*)(smem + OFF_W1L + nxt * 5120 + n * 80 + (koff + q * 4) * 2) = l;
            }
        }
        __syncthreads();
    }

    // ---- in-register: bias+relu+split -> stage-2 A fragments ----
    u32 A2H[2][4][4], A2L[2][4][4];
#pragma unroll
    for (int ks = 0; ks < 4; ks++) {
        int o0 = ks * 16 + (lane & 3) * 2;
        float b0 = __ldg(br + o0),     b1 = __ldg(br + o0 + 1);
        float b8 = __ldg(br + o0 + 8), b9 = __ldg(br + o0 + 9);
#pragma unroll
        for (int mi = 0; mi < 2; mi++) {
            const float* t0 = acc1[mi][2 * ks];
            const float* t1 = acc1[mi][2 * ks + 1];
            float v0 = fmaxf(t0[0] + b0, 0.f), v1 = fmaxf(t0[1] + b1, 0.f);
            float v2 = fmaxf(t0[2] + b0, 0.f), v3 = fmaxf(t0[3] + b1, 0.f);
            float w0 = fmaxf(t1[0] + b8, 0.f), w1 = fmaxf(t1[1] + b9, 0.f);
            float w2 = fmaxf(t1[2] + b8, 0.f), w3 = fmaxf(t1[3] + b9, 0.f);
            split2(v0, v1, A2H[mi][ks][0], A2L[mi][ks][0]);
            split2(v2, v3, A2H[mi][ks][1], A2L[mi][ks][1]);
            split2(w0, w1, A2H[mi][ks][2], A2L[mi][ks][2]);
            split2(w2, w3, A2H[mi][ks][3], A2L[mi][ks][3]);
        }
    }

    // ---- stage 2: N=144 (18 n-tiles), K=64 (4 k-steps) ----
    const char* wsph = smem + OFF_WSPH;
    const char* wspl = smem + OFF_WSPL;
    const int pxl = wid * 32 + (lane >> 2);
    float* kout = g_kmap + (size_t)(b * GKK) * HW + pt;
#pragma unroll 2
    for (int nj = 0; nj < 18; nj++) {
        float a2[2][4];
#pragma unroll
        for (int mi = 0; mi < 2; mi++)
#pragma unroll
            for (int q = 0; q < 4; q++) a2[mi][q] = 0.f;
#pragma unroll
        for (int ks = 0; ks < 4; ks++) {
            u32 off = bB2 + nj * 1152 + ks * 32;
            u32 bh0 = *(const u32*)(wsph + off);
            u32 bh1 = *(const u32*)(wsph + off + 16);
            u32 bl0 = *(const u32*)(wspl + off);
            u32 bl1 = *(const u32*)(wspl + off + 16);
#pragma unroll
            for (int mi = 0; mi < 2; mi++) {
                MMA(a2[mi], A2H[mi][ks], bh0, bh1);
                MMA(a2[mi], A2H[mi][ks], bl0, bl1);
                MMA(a2[mi], A2L[mi][ks], bh0, bh1);
            }
        }
        int o0 = nj * 8 + (lane & 3) * 2;
        float c0 = __ldg(bs + o0), c1 = __ldg(bs + o0 + 1);
#pragma unroll
        for (int mi = 0; mi < 2; mi++) {
            int px = pxl + mi * 16;
            kout[(size_t)o0 * HW + px]           = a2[mi][0] + c0;
            kout[(size_t)(o0 + 1) * HW + px]     = a2[mi][1] + c1;
            kout[(size_t)o0 * HW + px + 8]       = a2[mi][2] + c0;
            kout[(size_t)(o0 + 1) * HW + px + 8] = a2[mi][3] + c1;
        }
    }
}

// ---------------------------------------------------------------------------
// k_invol: unchanged from R6 (22us).
// ---------------------------------------------------------------------------
__global__ __launch_bounds__(256) void k_invol(const float* __restrict__ x,
                                               float* __restrict__ out) {
    __shared__ __align__(16) float sm[8 * 10 * 68 * 2];
    const int tid = threadIdx.x, strip = blockIdx.x, g = blockIdx.y, b = blockIdx.z;
    const int chbase = g * 16;
    const int cph = tid >> 7, rr = (tid >> 4) & 7, t4 = tid & 15;
    const int R0 = strip * 8 + rr, X0 = t4 * 4;

    const float* kbase = g_kmap + ((size_t)(b * G + g)) * KK * HW + R0 * IMG_W + X0;
    float4 km[9];
#pragma unroll
    for (int k = 0; k < 9; k++) km[k] = *(const float4*)(kbase + (size_t)k * HW);

    if (tid < 160) {
        int cp = tid / 20, rem = tid % 20;
        int r = rem >> 1, col = (rem & 1) ? 65 : 0;
        *(u64*)&sm[((cp * 10 + r) * 68 + col) * 2] = 0ull;
    }
#pragma unroll
    for (int it = 0; it < 5; it++) {
        int lin = tid + it * 256;
        int cp = lin / 160, rem = lin - cp * 160;
        int r = rem >> 4, c4 = rem & 15;
        int R = strip * 8 + r - 1;
        float4 a = make_float4(0.f, 0.f, 0.f, 0.f), c = a;
        if ((unsigned)R < (unsigned)IMG_H) {
            const float* p0 = x + ((size_t)(b * C + chbase + cp * 2)) * HW + R * IMG_W + c4 * 4;
            a = *(const float4*)p0;
            c = *(const float4*)(p0 + HW);
        }
        float* d = &sm[((cp * 10 + r) * 68 + 1 + c4 * 4) * 2];
        ((float2*)d)[0] = make_float2(a.x, c.x);
        ((float2*)d)[1] = make_float2(a.y, c.y);
        ((float2*)d)[2] = make_float2(a.z, c.z);
        ((float2*)d)[3] = make_float2(a.w, c.w);
    }
    __syncthreads();

#pragma unroll
    for (int half = 0; half < 2; half++) {
        u64 acc[2][4];
#pragma unroll
        for (int cp = 0; cp < 2; cp++)
#pragma unroll
            for (int j = 0; j < 4; j++) acc[cp][j] = 0ull;
#pragma unroll
        for (int dy = 0; dy < 3; dy++) {
            u64 km2[3][4];
#pragma unroll
            for (int dx = 0; dx < 3; dx++) {
                float4 kv = km[dy * 3 + dx];
                km2[dx][0] = pk(kv.x, kv.x); km2[dx][1] = pk(kv.y, kv.y);
                km2[dx][2] = pk(kv.z, kv.z); km2[dx][3] = pk(kv.w, kv.w);
            }
#pragma unroll
            for (int cp = 0; cp < 2; cp++) {
                const int cpi = cph * 4 + half * 2 + cp;
                const float* srow = &sm[((cpi * 10 + rr + dy) * 68 + t4 * 4) * 2];
                ulonglong2 q0 = *(const ulonglong2*)(srow);
                ulonglong2 q1 = *(const ulonglong2*)(srow + 4);
                ulonglong2 q2 = *(const ulonglong2*)(srow + 8);
                u64 p0 = q0.x, p1 = q0.y, p2 = q1.x, p3 = q1.y, p4 = q2.x, p5 = q2.y;
                acc[cp][0] = ffma2(p0, km2[0][0], acc[cp][0]);
                acc[cp][0] = ffma2(p1, km2[1][0], acc[cp][0]);
                acc[cp][0] = ffma2(p2, km2[2][0], acc[cp][0]);
                acc[cp][1] = ffma2(p1, km2[0][1], acc[cp][1]);
                acc[cp][1] = ffma2(p2, km2[1][1], acc[cp][1]);
                acc[cp][1] = ffma2(p3, km2[2][1], acc[cp][1]);
                acc[cp][2] = ffma2(p2, km2[0][2], acc[cp][2]);
                acc[cp][2] = ffma2(p3, km2[1][2], acc[cp][2]);
                acc[cp][2] = ffma2(p4, km2[2][2], acc[cp][2]);
                acc[cp][3] = ffma2(p3, km2[0][3], acc[cp][3]);
                acc[cp][3] = ffma2(p4, km2[1][3], acc[cp][3]);
                acc[cp][3] = ffma2(p5, km2[2][3], acc[cp][3]);
            }
        }
#pragma unroll
        for (int cp = 0; cp < 2; cp++) {
            const int ch = chbase + (cph * 4 + half * 2 + cp) * 2;
            float4 ev, od;
            ev.x = lo32(acc[cp][0]); od.x = hi32(acc[cp][0]);
            ev.y = lo32(acc[cp][1]); od.y = hi32(acc[cp][1]);
            ev.z = lo32(acc[cp][2]); od.z = hi32(acc[cp][2]);
            ev.w = lo32(acc[cp][3]); od.w = hi32(acc[cp][3]);
            float* ob = out + ((size_t)(b * C + ch)) * HW + R0 * IMG_W + X0;
            *(float4*)ob = ev;
            *(float4*)(ob + HW) = od;
        }
    }
}

// ---------------------------------------------------------------------------
extern "C" void kernel_launch(void* const* d_in, const int* in_sizes, int n_in,
                              void* d_out, int out_size) {
    const float* x   = (const float*)d_in[0];
    const float* wr  = (const float*)d_in[1];
    const float* br  = (const float*)d_in[2];
    const float* wsp = (const float*)d_in[3];
    const float* bs  = (const float*)d_in[4];
    float* out = (float*)d_out;

    static int once = 0;
    if (!once) {
        cudaFuncSetAttribute(k_gemm, cudaFuncAttributeMaxDynamicSharedMemorySize, SM_TOTAL);
        once = 1;
    }
    k_gemm<<<BB * (HW / 128), 128, SM_TOTAL>>>(x, wr, br, wsp, bs);
    dim3 g3(8, G, BB);
    k_invol<<<g3, 256>>>(x, out);
}